// round 5
// baseline (speedup 1.0000x reference)
#include <cuda_runtime.h>
#include <stdint.h>

// Classifier: out[r] = relu(hs0[r]@W1[VOCAB:] + W1[tk[r]] + b1) @ W2 + b2
// r in [0, 65536), HIDDEN=768, HS1=128.  tk is int32 (harness dtype contract).

#define HIDDEN 768
#define VOCAB  32000
#define HS1    128
#define BM     128
#define BK     16
#define NTHREADS 256
#define KTILES (HIDDEN / BK)   // 48

typedef unsigned long long ull;

// Packed fp32x2 FMA: d = a*b + d (elementwise on 2 packed floats).
// ptxas never emits FFMA2 from C++; only via this PTX (SASS_QUICKREF).
__device__ __forceinline__ void ffma2(ull &d, ull a, ull b) {
    asm("fma.rn.f32x2 %0, %1, %2, %0;" : "+l"(d) : "l"(a), "l"(b));
}
__device__ __forceinline__ ull fdup(float x) {
    ull r; asm("mov.b64 %0, {%1, %1};" : "=l"(r) : "f"(x)); return r;
}
__device__ __forceinline__ void funpack(float &lo, float &hi, ull v) {
    asm("mov.b64 {%0, %1}, %2;" : "=f"(lo), "=f"(hi) : "l"(v));
}

__global__ __launch_bounds__(NTHREADS, 2)
void classifier_kernel(const int* __restrict__ tk,
                       const float* __restrict__ hs0,
                       const float* __restrict__ W1,
                       const float* __restrict__ b1,
                       const float* __restrict__ W2,
                       const float* __restrict__ b2,
                       float* __restrict__ out,
                       int M)
{
    // A tile stored k-major, padded to kill STS bank conflicts on the transpose.
    __shared__ float As[BK][BM + 4];
    __shared__ float Ws[BK][HS1];
    __shared__ float sb1[HS1];
    __shared__ float sW2[HS1];

    const int tid = threadIdx.x;
    const int tx = tid & 15;        // N-direction (16 threads x 8 cols = 128)
    const int ty = tid >> 4;        // M-direction (16 threads x 8 rows = 128)
    const int m0 = blockIdx.x * BM;

    if (tid < HS1) { sb1[tid] = b1[tid]; sW2[tid] = W2[tid]; }

    const float* W1h = W1 + (size_t)VOCAB * HS1;

    ull acc[8][4];
    #pragma unroll
    for (int i = 0; i < 8; i++)
        #pragma unroll
        for (int j = 0; j < 4; j++) acc[i][j] = 0ull;

    float4 ra[2], rw[2];

    // ---- prologue: load k-tile 0 into registers, then smem ----
    #pragma unroll
    for (int u = 0; u < 2; u++) {
        int f = tid + u * 256;
        int m = f >> 2, kq = f & 3;              // A: 128 rows x 4 float4
        int row = m0 + m; if (row >= M) row = M - 1;
        ra[u] = *(const float4*)&hs0[(size_t)row * HIDDEN + kq * 4];
        int k = f >> 5, nq = f & 31;             // W: 16 k x 32 float4
        rw[u] = *(const float4*)&W1h[(size_t)k * HS1 + nq * 4];
    }
    #pragma unroll
    for (int u = 0; u < 2; u++) {
        int f = tid + u * 256;
        int m = f >> 2, kq = f & 3;
        As[kq * 4 + 0][m] = ra[u].x;
        As[kq * 4 + 1][m] = ra[u].y;
        As[kq * 4 + 2][m] = ra[u].z;
        As[kq * 4 + 3][m] = ra[u].w;
        int k = f >> 5, nq = f & 31;
        *(float4*)&Ws[k][nq * 4] = rw[u];
    }
    __syncthreads();

    // ---- main loop over 48 k-tiles, register-prefetch double buffering ----
    for (int kt = 0; kt < KTILES; kt++) {
        if (kt + 1 < KTILES) {
            #pragma unroll
            for (int u = 0; u < 2; u++) {
                int f = tid + u * 256;
                int m = f >> 2, kq = f & 3;
                int row = m0 + m; if (row >= M) row = M - 1;
                ra[u] = *(const float4*)&hs0[(size_t)row * HIDDEN + (kt + 1) * BK + kq * 4];
                int k = f >> 5, nq = f & 31;
                rw[u] = *(const float4*)&W1h[(size_t)((kt + 1) * BK + k) * HS1 + nq * 4];
            }
        }
        #pragma unroll
        for (int k = 0; k < BK; k++) {
            float4 a0 = *(const float4*)&As[k][ty * 8];
            float4 a1 = *(const float4*)&As[k][ty * 8 + 4];
            // B fragment as native 64-bit pairs (LDS.64, no packing needed)
            ull bp0 = *(const ull*)&Ws[k][tx * 8 + 0];
            ull bp1 = *(const ull*)&Ws[k][tx * 8 + 2];
            ull bp2 = *(const ull*)&Ws[k][tx * 8 + 4];
            ull bp3 = *(const ull*)&Ws[k][tx * 8 + 6];
            float av[8] = {a0.x, a0.y, a0.z, a0.w, a1.x, a1.y, a1.z, a1.w};
            #pragma unroll
            for (int i = 0; i < 8; i++) {
                ull ad = fdup(av[i]);
                ffma2(acc[i][0], ad, bp0);
                ffma2(acc[i][1], ad, bp1);
                ffma2(acc[i][2], ad, bp2);
                ffma2(acc[i][3], ad, bp3);
            }
        }
        __syncthreads();
        if (kt + 1 < KTILES) {
            #pragma unroll
            for (int u = 0; u < 2; u++) {
                int f = tid + u * 256;
                int m = f >> 2, kq = f & 3;
                As[kq * 4 + 0][m] = ra[u].x;
                As[kq * 4 + 1][m] = ra[u].y;
                As[kq * 4 + 2][m] = ra[u].z;
                As[kq * 4 + 3][m] = ra[u].w;
                int k = f >> 5, nq = f & 31;
                *(float4*)&Ws[k][nq * 4] = rw[u];
            }
            __syncthreads();
        }
    }

    // ---- epilogue: tok gather + bias + relu + dot(W2) + 16-lane reduction ----
    const float b2s = b2[0];
    #pragma unroll
    for (int i = 0; i < 8; i++) {
        int row = m0 + ty * 8 + i;
        float s = 0.f;
        if (row < M) {
            unsigned t = (unsigned)tk[row];
            if (t >= VOCAB) t = 0;                       // defensive: no-op if dtype right
            const float* wt = W1 + (size_t)t * HS1;      // one-hot gather row
            #pragma unroll
            for (int jp = 0; jp < 4; jp++) {
                float lo, hi;
                funpack(lo, hi, acc[i][jp]);
                int c0 = tx * 8 + jp * 2;
                float h0 = lo + wt[c0]     + sb1[c0];
                float h1 = hi + wt[c0 + 1] + sb1[c0 + 1];
                h0 = fmaxf(h0, 0.f);
                h1 = fmaxf(h1, 0.f);
                s += h0 * sW2[c0] + h1 * sW2[c0 + 1];
            }
        }
        // reduce across the 16 tx-lanes sharing this row (uniform control flow)
        #pragma unroll
        for (int off = 8; off >= 1; off >>= 1)
            s += __shfl_xor_sync(0xffffffffu, s, off);
        if (tx == 0 && row < M) out[row] = s + b2s;
    }
}

extern "C" void kernel_launch(void* const* d_in, const int* in_sizes, int n_in,
                              void* d_out, int out_size) {
    const int*   tk  = (const int*)d_in[0];             // int32 (jax downcasts int64)
    const float* hs0 = (const float*)d_in[1];
    const float* W1  = (const float*)d_in[2];           // [VOCAB+HIDDEN, HS1]
    const float* b1  = (const float*)d_in[3];
    const float* W2  = (const float*)d_in[4];
    const float* b2  = (const float*)d_in[5];
    float* out = (float*)d_out;

    int M = in_sizes[0];                                // 65536 rows
    int grid = (M + BM - 1) / BM;                       // 512 blocks
    classifier_kernel<<<grid, NTHREADS>>>(tk, hs0, W1, b1, W2, b2, out, M);
}

// round 11
// speedup vs baseline: 1.4917x; 1.4917x over previous
#include <cuda_runtime.h>
#include <cuda_bf16.h>
#include <stdint.h>

// out[r] = relu(hs0[r] @ W1[VOCAB:] + W1[tk[r]] + b1) @ W2 + b2
// M=65536, HIDDEN=768, HS1=128. mma.sync m16n8k16 bf16, 3-term split, fp32 acc.

#define HIDDEN   768
#define VOCAB    32000
#define HS1      128
#define BM       128
#define BK       64
#define NSTAGES  (HIDDEN / BK)   // 12
#define NTHREADS 256

// ---- smem layout (bytes). Tiles use padded stride 72 bf16 = 144 B ----
#define AST      144
#define SM_A_HI  0
#define SM_A_LO  18432
#define SM_W_HI  36864
#define SM_W_LO  55296
#define SM_B1    73728
#define SM_W2    74240
#define ACCST    132              // f32 stride for epilogue acc dump (reuses tile area)
#define SMEM_TOTAL 75776

// Pre-split W (hi/lo bf16, [n][k] layout) — shared by all CTAs, built once per launch.
__device__ __nv_bfloat16 gW_hi[HS1 * HIDDEN];
__device__ __nv_bfloat16 gW_lo[HS1 * HIDDEN];

__device__ __forceinline__ void bsplit(float x, __nv_bfloat16 &h, __nv_bfloat16 &l) {
    h = __float2bfloat16_rn(x);
    l = __float2bfloat16_rn(x - __bfloat162float(h));
}

__global__ void wsplit_kernel(const float* __restrict__ W1) {
    int i = blockIdx.x * blockDim.x + threadIdx.x;   // over HIDDEN*HS1
    if (i >= HIDDEN * HS1) return;
    int k = i >> 7, n = i & 127;
    float w = W1[(size_t)VOCAB * HS1 + (size_t)k * HS1 + n];
    __nv_bfloat16 h, l;
    bsplit(w, h, l);
    gW_hi[n * HIDDEN + k] = h;
    gW_lo[n * HIDDEN + k] = l;
}

// D += A(bf16) * B(bf16), m16n8k16, row.col, fp32 accumulate.
__device__ __forceinline__ void mma16816(float* d, const uint32_t* a, const uint32_t* b) {
    asm volatile(
        "mma.sync.aligned.m16n8k16.row.col.f32.bf16.bf16.f32 "
        "{%0,%1,%2,%3}, {%4,%5,%6,%7}, {%8,%9}, {%0,%1,%2,%3};"
        : "+f"(d[0]), "+f"(d[1]), "+f"(d[2]), "+f"(d[3])
        : "r"(a[0]), "r"(a[1]), "r"(a[2]), "r"(a[3]), "r"(b[0]), "r"(b[1]));
}

__global__ __launch_bounds__(NTHREADS)
void classifier_mma(const int* __restrict__ tk,
                    const float* __restrict__ hs0,
                    const float* __restrict__ W1,
                    const float* __restrict__ b1,
                    const float* __restrict__ W2,
                    const float* __restrict__ b2,
                    float* __restrict__ out,
                    int M)
{
    extern __shared__ char smem[];
    const int tid = threadIdx.x;
    const int wid = tid >> 5, lane = tid & 31;
    const int warp_m = wid & 3, warp_n = wid >> 2;   // 4 M-warps x 2 N-warps
    const int g = lane >> 2, tg = lane & 3;
    const int m0 = blockIdx.x * BM;

    if (tid < HS1) {
        *(float*)(smem + SM_B1 + tid * 4) = b1[tid];
        *(float*)(smem + SM_W2 + tid * 4) = W2[tid];
    }

    float acc[2][8][4];
    #pragma unroll
    for (int mt = 0; mt < 2; mt++)
        #pragma unroll
        for (int nt = 0; nt < 8; nt++)
            #pragma unroll
            for (int v = 0; v < 4; v++) acc[mt][nt][v] = 0.f;

    // prefetch registers: A = 32 f32 (8 float4), W = 64 bf16 (8 uint4: 4 hi + 4 lo)
    float4 pa[4][2];
    uint4  pw[8];
    const int a_row = (tid >> 3);               // 0..31 step over u
    const int a_seg = tid & 7;
    const int w_n   = tid >> 1;                 // 0..127
    const int w_kh  = tid & 1;

    // ---- prologue: LDG stage 0 ----
    {
        #pragma unroll
        for (int u = 0; u < 4; u++) {
            int row = a_row + u * 32;
            int r = m0 + row; if (r >= M) r = M - 1;
            const float4* p = (const float4*)&hs0[(size_t)r * HIDDEN + a_seg * 8];
            pa[u][0] = p[0]; pa[u][1] = p[1];
        }
        const uint4* ph = (const uint4*)&gW_hi[w_n * HIDDEN + w_kh * 32];
        const uint4* pl = (const uint4*)&gW_lo[w_n * HIDDEN + w_kh * 32];
        #pragma unroll
        for (int j = 0; j < 4; j++) { pw[j] = ph[j]; pw[4 + j] = pl[j]; }
    }
    // ---- STS stage 0 ----
    {
        #pragma unroll
        for (int u = 0; u < 4; u++) {
            int row = a_row + u * 32;
            float f[8] = {pa[u][0].x, pa[u][0].y, pa[u][0].z, pa[u][0].w,
                          pa[u][1].x, pa[u][1].y, pa[u][1].z, pa[u][1].w};
            __nv_bfloat162 hi2[4], lo2[4];
            #pragma unroll
            for (int j = 0; j < 4; j++) {
                __nv_bfloat16 h0, l0, h1, l1;
                bsplit(f[2 * j], h0, l0); bsplit(f[2 * j + 1], h1, l1);
                hi2[j] = __halves2bfloat162(h0, h1);
                lo2[j] = __halves2bfloat162(l0, l1);
            }
            uint32_t base = row * AST + a_seg * 16;
            *(uint4*)(smem + SM_A_HI + base) = *(uint4*)hi2;
            *(uint4*)(smem + SM_A_LO + base) = *(uint4*)lo2;
        }
        uint32_t wb = w_n * AST + w_kh * 64;
        #pragma unroll
        for (int j = 0; j < 4; j++) {
            *(uint4*)(smem + SM_W_HI + wb + j * 16) = pw[j];
            *(uint4*)(smem + SM_W_LO + wb + j * 16) = pw[4 + j];
        }
    }
    __syncthreads();

    // ---- main loop ----
    for (int s = 0; s < NSTAGES; s++) {
        // prefetch next stage (overlaps with MMA compute below)
        if (s + 1 < NSTAGES) {
            const int k1 = (s + 1) * BK;
            #pragma unroll
            for (int u = 0; u < 4; u++) {
                int row = a_row + u * 32;
                int r = m0 + row; if (r >= M) r = M - 1;
                const float4* p = (const float4*)&hs0[(size_t)r * HIDDEN + k1 + a_seg * 8];
                pa[u][0] = p[0]; pa[u][1] = p[1];
            }
            const uint4* ph = (const uint4*)&gW_hi[w_n * HIDDEN + k1 + w_kh * 32];
            const uint4* pl = (const uint4*)&gW_lo[w_n * HIDDEN + k1 + w_kh * 32];
            #pragma unroll
            for (int j = 0; j < 4; j++) { pw[j] = ph[j]; pw[4 + j] = pl[j]; }
        }

        // compute this stage: 4 k16 chunks x (2 mt x 8 nt x 3 split terms)
        #pragma unroll
        for (int kk = 0; kk < 4; kk++) {
            const uint32_t ka = kk * 32 + tg * 4;
            uint32_t ah[2][4], al[2][4];
            #pragma unroll
            for (int mt = 0; mt < 2; mt++) {
                uint32_t base = (warp_m * 32 + mt * 16 + g) * AST + ka;
                ah[mt][0] = *(const uint32_t*)(smem + SM_A_HI + base);
                ah[mt][1] = *(const uint32_t*)(smem + SM_A_HI + base + 8 * AST);
                ah[mt][2] = *(const uint32_t*)(smem + SM_A_HI + base + 16);
                ah[mt][3] = *(const uint32_t*)(smem + SM_A_HI + base + 8 * AST + 16);
                al[mt][0] = *(const uint32_t*)(smem + SM_A_LO + base);
                al[mt][1] = *(const uint32_t*)(smem + SM_A_LO + base + 8 * AST);
                al[mt][2] = *(const uint32_t*)(smem + SM_A_LO + base + 16);
                al[mt][3] = *(const uint32_t*)(smem + SM_A_LO + base + 8 * AST + 16);
            }
            uint32_t bh[8][2], bl[8][2];
            #pragma unroll
            for (int nt = 0; nt < 8; nt++) {
                uint32_t base = (warp_n * 64 + nt * 8 + g) * AST + ka;
                bh[nt][0] = *(const uint32_t*)(smem + SM_W_HI + base);
                bh[nt][1] = *(const uint32_t*)(smem + SM_W_HI + base + 16);
                bl[nt][0] = *(const uint32_t*)(smem + SM_W_LO + base);
                bl[nt][1] = *(const uint32_t*)(smem + SM_W_LO + base + 16);
            }
            #pragma unroll
            for (int mt = 0; mt < 2; mt++)
                #pragma unroll
                for (int nt = 0; nt < 8; nt++) {
                    mma16816(acc[mt][nt], ah[mt], bh[nt]);   // hi*hi
                    mma16816(acc[mt][nt], ah[mt], bl[nt]);   // hi*lo
                    mma16816(acc[mt][nt], al[mt], bh[nt]);   // lo*hi
                }
        }

        if (s + 1 < NSTAGES) {
            __syncthreads();
            #pragma unroll
            for (int u = 0; u < 4; u++) {
                int row = a_row + u * 32;
                float f[8] = {pa[u][0].x, pa[u][0].y, pa[u][0].z, pa[u][0].w,
                              pa[u][1].x, pa[u][1].y, pa[u][1].z, pa[u][1].w};
                __nv_bfloat162 hi2[4], lo2[4];
                #pragma unroll
                for (int j = 0; j < 4; j++) {
                    __nv_bfloat16 h0, l0, h1, l1;
                    bsplit(f[2 * j], h0, l0); bsplit(f[2 * j + 1], h1, l1);
                    hi2[j] = __halves2bfloat162(h0, h1);
                    lo2[j] = __halves2bfloat162(l0, l1);
                }
                uint32_t base = row * AST + a_seg * 16;
                *(uint4*)(smem + SM_A_HI + base) = *(uint4*)hi2;
                *(uint4*)(smem + SM_A_LO + base) = *(uint4*)lo2;
            }
            uint32_t wb = w_n * AST + w_kh * 64;
            #pragma unroll
            for (int j = 0; j < 4; j++) {
                *(uint4*)(smem + SM_W_HI + wb + j * 16) = pw[j];
                *(uint4*)(smem + SM_W_LO + wb + j * 16) = pw[4 + j];
            }
            __syncthreads();
        }
    }

    // ---- epilogue: dump acc to smem (f32, stride 132), then per-row fuse ----
    __syncthreads();                // all compute done; tile area reusable
    float* accb = (float*)smem;
    #pragma unroll
    for (int mt = 0; mt < 2; mt++)
        #pragma unroll
        for (int nt = 0; nt < 8; nt++) {
            int r = warp_m * 32 + mt * 16 + g;
            int c = warp_n * 64 + nt * 8 + tg * 2;
            *(float2*)&accb[r * ACCST + c]       = make_float2(acc[mt][nt][0], acc[mt][nt][1]);
            *(float2*)&accb[(r + 8) * ACCST + c] = make_float2(acc[mt][nt][2], acc[mt][nt][3]);
        }
    __syncthreads();

    if (tid < BM) {
        int row = m0 + tid;
        if (row < M) {
            unsigned t = (unsigned)tk[row];
            if (t >= VOCAB) t = 0;
            const float* wt  = W1 + (size_t)t * HS1;
            const float* b1s = (const float*)(smem + SM_B1);
            const float* w2s = (const float*)(smem + SM_W2);
            float s = 0.f;
            #pragma unroll 16
            for (int col = 0; col < HS1; col++) {
                float h = accb[tid * ACCST + col] + wt[col] + b1s[col];
                s += fmaxf(h, 0.f) * w2s[col];
            }
            out[row] = s + b2[0];
        }
    }
}

extern "C" void kernel_launch(void* const* d_in, const int* in_sizes, int n_in,
                              void* d_out, int out_size) {
    const int*   tk  = (const int*)d_in[0];
    const float* hs0 = (const float*)d_in[1];
    const float* W1  = (const float*)d_in[2];
    const float* b1  = (const float*)d_in[3];
    const float* W2  = (const float*)d_in[4];
    const float* b2  = (const float*)d_in[5];
    float* out = (float*)d_out;

    int M = in_sizes[0];                          // 65536
    int grid = (M + BM - 1) / BM;                 // 512

    wsplit_kernel<<<(HIDDEN * HS1 + 255) / 256, 256>>>(W1);
    cudaFuncSetAttribute(classifier_mma, cudaFuncAttributeMaxDynamicSharedMemorySize, SMEM_TOTAL);
    classifier_mma<<<grid, NTHREADS, SMEM_TOTAL>>>(tk, hs0, W1, b1, W2, b2, out, M);
}